// round 4
// baseline (speedup 1.0000x reference)
#include <cuda_runtime.h>
#include <cstdint>
#include <math.h>

#define B_TOTAL 32768
#define NSLOT   5
#define D_IN    512
#define DK      16
#define NV      7
#define TB      256                 // batches per block
#define DSUP    16                  // d-values per staging superstep
#define NSTEP   (D_IN / DSUP)       // 32
#define TROW    260                 // padded transposed-tile row
#define SM_W    (D_IN * DK)         // 8192 floats
#define SM_TILE (DSUP * TROW)       // 4160 floats
#define SMEM_FLOATS (SM_W + 2 * SM_TILE)
#define SMEM_BYTES  (SMEM_FLOATS * 4)   // 66048 B -> 3 blocks/SM

typedef unsigned long long ull;

// projection scratch: P[v][b][k]; v: 0,1 = read slots 0,1; 2..6 = write slots 0..4
__device__ float g_P[NV][B_TOTAL][DK];

__device__ __forceinline__ void fma2(ull& d, ull a, ull b) {
    asm("fma.rn.f32x2 %0, %1, %2, %0;" : "+l"(d) : "l"(a), "l"(b));
}
__device__ __forceinline__ ull pack2(float x) {
    ull r; asm("mov.b64 %0, {%1, %1};" : "=l"(r) : "f"(x)); return r;
}

// ---------------------------------------------------------------------------
// Kernel 1: block-diagonal projection. grid = (128, 7), 128 threads.
// Thread tile: 4 batches x 8 k, f32x2 paired along k (w operand native u64).
// ---------------------------------------------------------------------------
__global__ __launch_bounds__(128, 3) void proj_kernel(
    const float* __restrict__ q, const float* __restrict__ kk,
    const float* __restrict__ wr, const float* __restrict__ ww)
{
    extern __shared__ float sh[];
    float* sW    = sh;            // [512][16]
    float* tiles = sh + SM_W;     // [2][DSUP][TROW], transposed: tile[d_local][batch]

    const int v = blockIdx.y;
    const float* src; const float* W; int slot;
    if (v < 2) { src = q;  slot = v;     W = wr + (size_t)v * D_IN * DK; }
    else       { src = kk; slot = v - 2; W = ww + (size_t)(v - 2) * D_IN * DK; }
    const int b0  = blockIdx.x * TB;
    const int tid = threadIdx.x;

    // stage W into smem (8192 floats)
    {
        const float4* Ws = (const float4*)W;
        float4*       Wd = (float4*)sW;
        #pragma unroll
        for (int i = 0; i < 16; i++) Wd[tid + i * 128] = Ws[tid + i * 128];
    }

    // Staging geometry: 4 lanes cover 64B of one batch row; 32 rows per pass,
    // 8 passes cover TB=256 rows per superstep of 16 d-values.
    const int rbase = tid >> 2;          // 0..31
    const int c4    = tid & 3;           // 16B chunk within 64B
    const float* gbase = src + (size_t)(b0 + rbase) * (NSLOT * D_IN)
                             + (size_t)slot * D_IN + c4 * 4;
    const size_t rowstride = (size_t)32 * NSLOT * D_IN;   // 32 batch-rows per pass

    float4 pf[8];

    // ---- stage step 0 into buffer 0 ----
    #pragma unroll
    for (int j = 0; j < 8; j++)
        pf[j] = *(const float4*)(gbase + (size_t)j * rowstride);
    #pragma unroll
    for (int j = 0; j < 8; j++) {
        int r = rbase + j * 32;
        tiles[(c4 * 4 + 0) * TROW + r] = pf[j].x;
        tiles[(c4 * 4 + 1) * TROW + r] = pf[j].y;
        tiles[(c4 * 4 + 2) * TROW + r] = pf[j].z;
        tiles[(c4 * 4 + 3) * TROW + r] = pf[j].w;
    }
    __syncthreads();

    const int k0 = (tid & 1) * 8;        // 2 k-groups of 8
    const int bb = (tid >> 1) * 4;       // 64 batch-groups of 4

    ull acc[4][4];                       // [batch][k-pair]; pair = (k even, k odd)
    #pragma unroll
    for (int b = 0; b < 4; b++)
        #pragma unroll
        for (int j = 0; j < 4; j++) acc[b][j] = 0ull;

    for (int s = 0; s < NSTEP; s++) {
        const float* tb = tiles + (s & 1) * SM_TILE;
        float*       tn = tiles + ((s + 1) & 1) * SM_TILE;
        const bool more = (s + 1) < NSTEP;

        // prefetch next superstep into registers
        if (more) {
            const int d0n = (s + 1) * DSUP;
            #pragma unroll
            for (int j = 0; j < 8; j++)
                pf[j] = *(const float4*)(gbase + (size_t)j * rowstride + d0n);
        }

        // compute current superstep
        #pragma unroll
        for (int dd = 0; dd < DSUP; dd++) {
            float4 qv = *(const float4*)(tb + dd * TROW + bb);
            const ulonglong2* wp =
                (const ulonglong2*)(sW + (s * DSUP + dd) * DK + k0);
            ulonglong2 wa = wp[0], wb = wp[1];   // native k-pairs, no packing
            ull q0 = pack2(qv.x), q1 = pack2(qv.y),
                q2 = pack2(qv.z), q3 = pack2(qv.w);
            fma2(acc[0][0], q0, wa.x); fma2(acc[0][1], q0, wa.y);
            fma2(acc[0][2], q0, wb.x); fma2(acc[0][3], q0, wb.y);
            fma2(acc[1][0], q1, wa.x); fma2(acc[1][1], q1, wa.y);
            fma2(acc[1][2], q1, wb.x); fma2(acc[1][3], q1, wb.y);
            fma2(acc[2][0], q2, wa.x); fma2(acc[2][1], q2, wa.y);
            fma2(acc[2][2], q2, wb.x); fma2(acc[2][3], q2, wb.y);
            fma2(acc[3][0], q3, wa.x); fma2(acc[3][1], q3, wa.y);
            fma2(acc[3][2], q3, wb.x); fma2(acc[3][3], q3, wb.y);
        }

        // store prefetched data into the other buffer
        if (more) {
            #pragma unroll
            for (int j = 0; j < 8; j++) {
                int r = rbase + j * 32;
                tn[(c4 * 4 + 0) * TROW + r] = pf[j].x;
                tn[(c4 * 4 + 1) * TROW + r] = pf[j].y;
                tn[(c4 * 4 + 2) * TROW + r] = pf[j].z;
                tn[(c4 * 4 + 3) * TROW + r] = pf[j].w;
            }
            __syncthreads();
        }
    }

    // acc layout IS the output row layout: k-pairs contiguous
    #pragma unroll
    for (int b = 0; b < 4; b++) {
        ull* dst = (ull*)&g_P[v][b0 + bb + b][k0];
        ulonglong2 lo; lo.x = acc[b][0]; lo.y = acc[b][1];
        ulonglong2 hi; hi.x = acc[b][2]; hi.y = acc[b][3];
        ((ulonglong2*)dst)[0] = lo;
        ((ulonglong2*)dst)[1] = hi;
    }
}

// ---------------------------------------------------------------------------
// Kernel 2: scores + threefry gumbel + argmax -> one-hot outputs
// ---------------------------------------------------------------------------
__device__ __forceinline__ uint32_t rotl32(uint32_t x, int r) {
    return (x << r) | (x >> (32 - r));
}

__device__ __forceinline__ uint32_t threefry_bits(uint32_t key, uint32_t ctr)
{
    const uint32_t ks0 = 0u, ks1 = key, ks2 = 0x1BD11BDAu ^ key;
    uint32_t x0 = ks0;
    uint32_t x1 = ctr + ks1;
#define R4(a,b,cc,d)                                   \
    x0 += x1; x1 = rotl32(x1,(a));  x1 ^= x0;          \
    x0 += x1; x1 = rotl32(x1,(b));  x1 ^= x0;          \
    x0 += x1; x1 = rotl32(x1,(cc)); x1 ^= x0;          \
    x0 += x1; x1 = rotl32(x1,(d));  x1 ^= x0;
    R4(13,15,26,6);   x0 += ks1; x1 += ks2 + 1u;
    R4(17,29,16,24);  x0 += ks2; x1 += ks0 + 2u;
    R4(13,15,26,6);   x0 += ks0; x1 += ks1 + 3u;
    R4(17,29,16,24);  x0 += ks1; x1 += ks2 + 4u;
    R4(13,15,26,6);   x0 += ks2; x1 += ks0 + 5u;
#undef R4
    return x0 ^ x1;
}

__device__ __forceinline__ float gumbel_from_bits(uint32_t bits)
{
    float u = __uint_as_float((bits >> 9) | 0x3f800000u) - 1.0f;
    float val = fmaxf(1e-10f, u * (1.0f - 1e-10f) + 1e-10f);
    return -logf(-logf(val));
}

__global__ __launch_bounds__(128) void score_kernel(float* __restrict__ out)
{
    const int b = blockIdx.x * blockDim.x + threadIdx.x;
    if (b >= B_TOTAL) return;

    float r0[DK], r1[DK];
    #pragma unroll
    for (int t = 0; t < 4; t++) {
        ((float4*)r0)[t] = ((const float4*)&g_P[0][b][0])[t];
        ((float4*)r1)[t] = ((const float4*)&g_P[1][b][0])[t];
    }

    float z0[NSLOT], z1[NSLOT];
    #pragma unroll
    for (int m = 0; m < NSLOT; m++) {
        float wv[DK];
        #pragma unroll
        for (int t = 0; t < 4; t++)
            ((float4*)wv)[t] = ((const float4*)&g_P[2 + m][b][0])[t];

        float s0 = 0.0f, s1 = 0.0f;
        #pragma unroll
        for (int t = 0; t < DK; t++) {
            s0 = fmaf(r0[t], wv[t], s0);
            s1 = fmaf(r1[t], wv[t], s1);
        }
        s0 *= 0.25f;
        s1 *= 0.25f;

        const uint32_t ctr = (uint32_t)(b * NSLOT + m);
        z0[m] = s0 + gumbel_from_bits(threefry_bits(42u, ctr));
        z1[m] = s1 + gumbel_from_bits(threefry_bits(43u, ctr));
    }

    int a0 = 0, a1 = 0;
    float b0v = z0[0], b1v = z1[0];
    #pragma unroll
    for (int m = 1; m < NSLOT; m++) {
        if (z0[m] > b0v) { b0v = z0[m]; a0 = m; }
        if (z1[m] > b1v) { b1v = z1[m]; a1 = m; }
    }

    float* o1 = out + (size_t)b * NSLOT;
    float* o2 = out + (size_t)B_TOTAL * NSLOT + (size_t)b * NSLOT;
    #pragma unroll
    for (int m = 0; m < NSLOT; m++) {
        o1[m] = (m == a0) ? 1.0f : 0.0f;
        o2[m] = (m == a1) ? 1.0f : 0.0f;
    }
}

// ---------------------------------------------------------------------------
extern "C" void kernel_launch(void* const* d_in, const int* in_sizes, int n_in,
                              void* d_out, int out_size)
{
    const float* q  = (const float*)d_in[0];
    const float* kk = (const float*)d_in[1];
    const float* wr = (const float*)d_in[2];
    const float* ww = (const float*)d_in[3];
    float* out = (float*)d_out;

    cudaFuncSetAttribute(proj_kernel,
                         cudaFuncAttributeMaxDynamicSharedMemorySize, SMEM_BYTES);

    dim3 grid1(B_TOTAL / TB, NV);
    proj_kernel<<<grid1, 128, SMEM_BYTES>>>(q, kk, wr, ww);

    score_kernel<<<B_TOTAL / 128, 128>>>(out);
}

// round 5
// speedup vs baseline: 1.2579x; 1.2579x over previous
#include <cuda_runtime.h>
#include <cstdint>
#include <math.h>

#define B_TOTAL 32768
#define NSLOT   5
#define D_IN    512
#define DK      16
#define NV      7
#define TB      512                 // batches per block
#define DSUP    8                   // d-values per staging superstep
#define NSTEP   (D_IN / DSUP)       // 64
#define TROW    516                 // padded transposed-tile row
#define SM_W    (D_IN * DK)         // 8192 floats
#define SM_TILE (DSUP * TROW)       // 4128 floats
#define SMEM_FLOATS (SM_W + 2 * SM_TILE)
#define SMEM_BYTES  (SMEM_FLOATS * 4)   // 65792 B -> 3 blocks/SM

typedef unsigned long long ull;

// projection scratch: P[v][b][k]; v: 0,1 = read slots 0,1; 2..6 = write slots 0..4
__device__ float g_P[NV][B_TOTAL][DK];

__device__ __forceinline__ void fma2(ull& d, ull a, ull b) {
    asm("fma.rn.f32x2 %0, %1, %2, %0;" : "+l"(d) : "l"(a), "l"(b));
}
__device__ __forceinline__ ull pack2(float x) {
    ull r; asm("mov.b64 %0, {%1, %1};" : "=l"(r) : "f"(x)); return r;
}
__device__ __forceinline__ void unpack2(ull a, float& lo, float& hi) {
    asm("mov.b64 {%0, %1}, %2;" : "=f"(lo), "=f"(hi) : "l"(a));
}

// ---------------------------------------------------------------------------
// Kernel 1: block-diagonal projection (R3 structure, 3 blocks/SM)
// grid = (64, 7), 128 threads. 8 batch x 8 k register tile, batch-paired f32x2.
// ---------------------------------------------------------------------------
__global__ __launch_bounds__(128, 3) void proj_kernel(
    const float* __restrict__ q, const float* __restrict__ kk,
    const float* __restrict__ wr, const float* __restrict__ ww)
{
    extern __shared__ float sh[];
    float* sW    = sh;            // [512][16]
    float* tiles = sh + SM_W;     // [2][DSUP][TROW], transposed: tile[d_local][batch]

    const int v = blockIdx.y;
    const float* src; const float* W; int slot;
    if (v < 2) { src = q;  slot = v;     W = wr + (size_t)v * D_IN * DK; }
    else       { src = kk; slot = v - 2; W = ww + (size_t)(v - 2) * D_IN * DK; }
    const int b0  = blockIdx.x * TB;
    const int tid = threadIdx.x;
    const int lan = tid & 31;
    const int wrp = tid >> 5;

    // stage W into smem (8192 floats)
    {
        const float4* Ws = (const float4*)W;
        float4*       Wd = (float4*)sW;
        #pragma unroll
        for (int i = 0; i < 16; i++) Wd[tid + i * 128] = Ws[tid + i * 128];
    }

    // Staging geometry: 2 lanes cover 32B (8 floats = one DSUP chunk) of one
    // batch row. Warp covers 16 rows per load instr; 8 J-steps cover 128 rows.
    const int rbase = wrp * 128 + (lan >> 1);
    const int c2    = lan & 1;           // which 16B half of the 32B chunk
    const float* gbase = src + (size_t)(b0 + rbase) * (NSLOT * D_IN)
                             + (size_t)slot * D_IN + c2 * 4;
    const size_t rowstride = (size_t)16 * NSLOT * D_IN;   // 16 batch-rows per J

    float4 pf[4];

    // ---- stage superstep 0 into buffer 0 ----
    #pragma unroll
    for (int half = 0; half < 2; half++) {
        #pragma unroll
        for (int j = 0; j < 4; j++)
            pf[j] = *(const float4*)(gbase + (size_t)(half * 4 + j) * rowstride);
        #pragma unroll
        for (int j = 0; j < 4; j++) {
            int r = rbase + (half * 4 + j) * 16;
            tiles[(c2 * 4 + 0) * TROW + r] = pf[j].x;
            tiles[(c2 * 4 + 1) * TROW + r] = pf[j].y;
            tiles[(c2 * 4 + 2) * TROW + r] = pf[j].z;
            tiles[(c2 * 4 + 3) * TROW + r] = pf[j].w;
        }
    }
    __syncthreads();

    const int kg = tid & 1;        // 2 k-groups of 8
    const int bg = tid >> 1;       // 64 batch-groups of 8
    const int k0 = kg * 8;
    const int bb = bg * 8;

    ull acc[4][8];                 // [batch-pair][k]  (pairs along batch)
    #pragma unroll
    for (int p = 0; p < 4; p++)
        #pragma unroll
        for (int j = 0; j < 8; j++) acc[p][j] = 0ull;

    for (int s = 0; s < NSTEP; s++) {
        const float* tb = tiles + (s & 1) * SM_TILE;
        float*       tn = tiles + ((s + 1) & 1) * SM_TILE;
        const bool more = (s + 1) < NSTEP;
        const int d0n = (s + 1) * DSUP;

        // prefetch half A of next superstep
        if (more) {
            #pragma unroll
            for (int j = 0; j < 4; j++)
                pf[j] = *(const float4*)(gbase + (size_t)j * rowstride + d0n);
        }

        // compute dd = 0..3
        #pragma unroll
        for (int dd = 0; dd < 4; dd++) {
            const ulonglong2* qp = (const ulonglong2*)(tb + dd * TROW + bb);
            ulonglong2 qa = qp[0], qb = qp[1];       // batches bb..bb+7, 4 pairs
            const float4* wrow = (const float4*)(sW + (s * DSUP + dd) * DK + k0);
            float4 wa = wrow[0], wb = wrow[1];
            ull wp[8] = { pack2(wa.x), pack2(wa.y), pack2(wa.z), pack2(wa.w),
                          pack2(wb.x), pack2(wb.y), pack2(wb.z), pack2(wb.w) };
            #pragma unroll
            for (int j = 0; j < 8; j++) {
                fma2(acc[0][j], qa.x, wp[j]);
                fma2(acc[1][j], qa.y, wp[j]);
                fma2(acc[2][j], qb.x, wp[j]);
                fma2(acc[3][j], qb.y, wp[j]);
            }
        }

        if (more) {
            // store half A of next superstep, then prefetch half B
            #pragma unroll
            for (int j = 0; j < 4; j++) {
                int r = rbase + j * 16;
                tn[(c2 * 4 + 0) * TROW + r] = pf[j].x;
                tn[(c2 * 4 + 1) * TROW + r] = pf[j].y;
                tn[(c2 * 4 + 2) * TROW + r] = pf[j].z;
                tn[(c2 * 4 + 3) * TROW + r] = pf[j].w;
            }
            #pragma unroll
            for (int j = 0; j < 4; j++)
                pf[j] = *(const float4*)(gbase + (size_t)(4 + j) * rowstride + d0n);
        }

        // compute dd = 4..7
        #pragma unroll
        for (int dd = 4; dd < 8; dd++) {
            const ulonglong2* qp = (const ulonglong2*)(tb + dd * TROW + bb);
            ulonglong2 qa = qp[0], qb = qp[1];
            const float4* wrow = (const float4*)(sW + (s * DSUP + dd) * DK + k0);
            float4 wa = wrow[0], wb = wrow[1];
            ull wp[8] = { pack2(wa.x), pack2(wa.y), pack2(wa.z), pack2(wa.w),
                          pack2(wb.x), pack2(wb.y), pack2(wb.z), pack2(wb.w) };
            #pragma unroll
            for (int j = 0; j < 8; j++) {
                fma2(acc[0][j], qa.x, wp[j]);
                fma2(acc[1][j], qa.y, wp[j]);
                fma2(acc[2][j], qb.x, wp[j]);
                fma2(acc[3][j], qb.y, wp[j]);
            }
        }

        if (more) {
            #pragma unroll
            for (int j = 0; j < 4; j++) {
                int r = rbase + (4 + j) * 16;
                tn[(c2 * 4 + 0) * TROW + r] = pf[j].x;
                tn[(c2 * 4 + 1) * TROW + r] = pf[j].y;
                tn[(c2 * 4 + 2) * TROW + r] = pf[j].z;
                tn[(c2 * 4 + 3) * TROW + r] = pf[j].w;
            }
            __syncthreads();
        }
    }

    // write results: batch-pair p holds batches (bb+2p, bb+2p+1)
    #pragma unroll
    for (int p = 0; p < 4; p++) {
        float lo[8], hi[8];
        #pragma unroll
        for (int j = 0; j < 8; j++) unpack2(acc[p][j], lo[j], hi[j]);
        float* d0 = &g_P[v][b0 + bb + 2 * p][k0];
        float* d1 = &g_P[v][b0 + bb + 2 * p + 1][k0];
        *(float4*)(d0)     = make_float4(lo[0], lo[1], lo[2], lo[3]);
        *(float4*)(d0 + 4) = make_float4(lo[4], lo[5], lo[6], lo[7]);
        *(float4*)(d1)     = make_float4(hi[0], hi[1], hi[2], hi[3]);
        *(float4*)(d1 + 4) = make_float4(hi[4], hi[5], hi[6], hi[7]);
    }
}

// ---------------------------------------------------------------------------
// Kernel 2: scores + threefry gumbel + argmax -> one-hot outputs
// ---------------------------------------------------------------------------
__device__ __forceinline__ uint32_t rotl32(uint32_t x, int r) {
    return (x << r) | (x >> (32 - r));
}

__device__ __forceinline__ uint32_t threefry_bits(uint32_t key, uint32_t ctr)
{
    const uint32_t ks0 = 0u, ks1 = key, ks2 = 0x1BD11BDAu ^ key;
    uint32_t x0 = ks0;
    uint32_t x1 = ctr + ks1;
#define R4(a,b,cc,d)                                   \
    x0 += x1; x1 = rotl32(x1,(a));  x1 ^= x0;          \
    x0 += x1; x1 = rotl32(x1,(b));  x1 ^= x0;          \
    x0 += x1; x1 = rotl32(x1,(cc)); x1 ^= x0;          \
    x0 += x1; x1 = rotl32(x1,(d));  x1 ^= x0;
    R4(13,15,26,6);   x0 += ks1; x1 += ks2 + 1u;
    R4(17,29,16,24);  x0 += ks2; x1 += ks0 + 2u;
    R4(13,15,26,6);   x0 += ks0; x1 += ks1 + 3u;
    R4(17,29,16,24);  x0 += ks1; x1 += ks2 + 4u;
    R4(13,15,26,6);   x0 += ks2; x1 += ks0 + 5u;
#undef R4
    return x0 ^ x1;
}

__device__ __forceinline__ float gumbel_from_bits(uint32_t bits)
{
    float u = __uint_as_float((bits >> 9) | 0x3f800000u) - 1.0f;
    float val = fmaxf(1e-10f, u * (1.0f - 1e-10f) + 1e-10f);
    return -logf(-logf(val));
}

__global__ __launch_bounds__(64) void score_kernel(float* __restrict__ out)
{
    const int b = blockIdx.x * blockDim.x + threadIdx.x;
    if (b >= B_TOTAL) return;

    float r0[DK], r1[DK];
    #pragma unroll
    for (int t = 0; t < 4; t++) {
        ((float4*)r0)[t] = ((const float4*)&g_P[0][b][0])[t];
        ((float4*)r1)[t] = ((const float4*)&g_P[1][b][0])[t];
    }

    float z0[NSLOT], z1[NSLOT];
    #pragma unroll
    for (int m = 0; m < NSLOT; m++) {
        float wv[DK];
        #pragma unroll
        for (int t = 0; t < 4; t++)
            ((float4*)wv)[t] = ((const float4*)&g_P[2 + m][b][0])[t];

        float s0 = 0.0f, s1 = 0.0f;
        #pragma unroll
        for (int t = 0; t < DK; t++) {
            s0 = fmaf(r0[t], wv[t], s0);
            s1 = fmaf(r1[t], wv[t], s1);
        }
        s0 *= 0.25f;
        s1 *= 0.25f;

        const uint32_t ctr = (uint32_t)(b * NSLOT + m);
        z0[m] = s0 + gumbel_from_bits(threefry_bits(42u, ctr));
        z1[m] = s1 + gumbel_from_bits(threefry_bits(43u, ctr));
    }

    int a0 = 0, a1 = 0;
    float b0v = z0[0], b1v = z1[0];
    #pragma unroll
    for (int m = 1; m < NSLOT; m++) {
        if (z0[m] > b0v) { b0v = z0[m]; a0 = m; }
        if (z1[m] > b1v) { b1v = z1[m]; a1 = m; }
    }

    float* o1 = out + (size_t)b * NSLOT;
    float* o2 = out + (size_t)B_TOTAL * NSLOT + (size_t)b * NSLOT;
    #pragma unroll
    for (int m = 0; m < NSLOT; m++) {
        o1[m] = (m == a0) ? 1.0f : 0.0f;
        o2[m] = (m == a1) ? 1.0f : 0.0f;
    }
}

// ---------------------------------------------------------------------------
extern "C" void kernel_launch(void* const* d_in, const int* in_sizes, int n_in,
                              void* d_out, int out_size)
{
    const float* q  = (const float*)d_in[0];
    const float* kk = (const float*)d_in[1];
    const float* wr = (const float*)d_in[2];
    const float* ww = (const float*)d_in[3];
    float* out = (float*)d_out;

    cudaFuncSetAttribute(proj_kernel,
                         cudaFuncAttributeMaxDynamicSharedMemorySize, SMEM_BYTES);

    dim3 grid1(B_TOTAL / TB, NV);
    proj_kernel<<<grid1, 128, SMEM_BYTES>>>(q, kk, wr, ww);

    score_kernel<<<B_TOTAL / 64, 64>>>(out);
}

// round 7
// speedup vs baseline: 1.6693x; 1.3270x over previous
#include <cuda_runtime.h>
#include <cuda_bf16.h>
#include <cstdint>
#include <math.h>

#define B_TOTAL 32768
#define NSLOT   5
#define D_IN    512
#define DK      16
#define NV      7
#define MT      256          // batches per block
#define NCHK    (D_IN / 16)  // 32 k-chunks of 16
#define THREADS 256

// projection scratch: P[v][b][k]; v: 0,1 = read slots; 2..6 = write slots
__device__ float g_P[NV][B_TOTAL][DK];

// ---------------------------------------------------------------------------
// 3-way bf16 split of an fp32 pair; e0 -> low half of each bf16x2.
// ---------------------------------------------------------------------------
static __device__ __forceinline__ void split3(float e0, float e1,
                                              uint32_t& h, uint32_t& m, uint32_t& l) {
    asm("cvt.rn.bf16x2.f32 %0, %1, %2;" : "=r"(h) : "f"(e1), "f"(e0));
    float h0 = __uint_as_float(h << 16);
    float h1 = __uint_as_float(h & 0xFFFF0000u);
    float r0 = e0 - h0, r1 = e1 - h1;
    asm("cvt.rn.bf16x2.f32 %0, %1, %2;" : "=r"(m) : "f"(r1), "f"(r0));
    float m0 = __uint_as_float(m << 16);
    float m1 = __uint_as_float(m & 0xFFFF0000u);
    float s0 = r0 - m0, s1 = r1 - m1;
    asm("cvt.rn.bf16x2.f32 %0, %1, %2;" : "=r"(l) : "f"(s1), "f"(s0));
}

static __device__ __forceinline__ void mma16816(float* d, const uint32_t* a, uint2 b) {
    asm volatile(
        "mma.sync.aligned.m16n8k16.row.col.f32.bf16.bf16.f32 "
        "{%0,%1,%2,%3}, {%4,%5,%6,%7}, {%8,%9}, {%0,%1,%2,%3};"
        : "+f"(d[0]), "+f"(d[1]), "+f"(d[2]), "+f"(d[3])
        : "r"(a[0]), "r"(a[1]), "r"(a[2]), "r"(a[3]), "r"(b.x), "r"(b.y));
}

// ---------------------------------------------------------------------------
// Kernel 1: projection GEMM on HMMA (mma.sync m16n8k16 bf16, fp32 emulated via
// 3-way split, 6 passes). grid = (128, 7), 256 threads (8 warps x 32 batches).
//
// K-permutation inside each 16-chunk: fragment slot (t4=lane&3, s, h) is fed
// memory column d = chunk*16 + t4*4 + 2h + s, so the A fragment is one float4
// per (row, t4). B fragments (from W) use the same permutation and are
// precomputed in per-lane order in smem.
// ---------------------------------------------------------------------------
__global__ __launch_bounds__(THREADS) void proj_kernel(
    const float* __restrict__ q, const float* __restrict__ kk,
    const float* __restrict__ wr, const float* __restrict__ ww)
{
    // sB[c][plane][ntile][lane][reg] : uint32 bf16x2 fragment words
    __shared__ uint32_t sB[NCHK * 3 * 2 * 32 * 2];    // 48 KB

    const int tid = threadIdx.x;
    const int lane = tid & 31;
    const int wid  = tid >> 5;
    const int g  = lane >> 2;      // groupID (row within m8)
    const int t4 = lane & 3;

    const int v = blockIdx.y;
    const float* src; const float* W; int slot;
    if (v < 2) { src = q;  slot = v;     W = wr + (size_t)v * D_IN * DK; }
    else       { src = kk; slot = v - 2; W = ww + (size_t)(v - 2) * D_IN * DK; }
    const int bbase = blockIdx.x * MT;

    // ---- stage B fragments: item i = ((c*2 + nt)*32 + lane_w)*2 + reg ----
    #pragma unroll
    for (int it = 0; it < 16; it++) {
        int i    = tid + it * THREADS;      // 0..4095
        int reg  = i & 1;
        int ln   = (i >> 1) & 31;
        int nt   = (i >> 6) & 1;
        int c    = i >> 7;
        int d    = c * 16 + (ln & 3) * 4 + reg * 2;
        int n    = nt * 8 + (ln >> 2);
        float w0 = W[d * DK + n];
        float w1 = W[(d + 1) * DK + n];
        uint32_t h, m, l;
        split3(w0, w1, h, m, l);
        // word index: (((c*3 + plane)*2 + nt)*32 + ln)*2 + reg
        int base = ((c * 3 * 2 + nt) * 32 + ln) * 2 + reg;
        sB[base]            = h;
        sB[base + 2 * 64]   = m;    // plane stride = 2*32*2 = 128 words... careful:
        sB[base + 4 * 64]   = l;
    }
    __syncthreads();

    // NOTE plane stride: layout is [c][plane][nt][lane][reg]:
    //   idx = ((((c*3)+p)*2+nt)*32+ln)*2+reg ; plane stride = 2*32*2 = 128 words.
    // The staging above used base with p=0 and added p*128 words (2*64). OK.

    // A pointers: warp handles rows wid*32 + {g, g+8, g+16, g+24}
    const float* ap[4];
    #pragma unroll
    for (int rh = 0; rh < 4; rh++) {
        int row = bbase + wid * 32 + rh * 8 + g;
        ap[rh] = src + (size_t)row * (NSLOT * D_IN) + (size_t)slot * D_IN + t4 * 4;
    }

    float acc[2][2][4];
    #pragma unroll
    for (int mt = 0; mt < 2; mt++)
        #pragma unroll
        for (int nt = 0; nt < 2; nt++)
            #pragma unroll
            for (int j = 0; j < 4; j++) acc[mt][nt][j] = 0.0f;

    static const int PA[6] = {0, 0, 1, 0, 2, 1};
    static const int PB[6] = {0, 1, 0, 2, 0, 1};

    for (int c = 0; c < NCHK; c++) {
        // load 4 float4 (2 m-tiles x 2 row-halves)
        float4 f[4];
        #pragma unroll
        for (int rh = 0; rh < 4; rh++)
            f[rh] = *(const float4*)(ap[rh] + c * 16);

        // convert to fragment planes: afr[plane][mtile][reg 0..3]
        // reg0 = (rowlow, h=0) from (x,y); reg2 = (rowlow, h=1) from (z,w);
        // reg1/reg3 = rowhigh.
        uint32_t afr[3][2][4];
        #pragma unroll
        for (int mt = 0; mt < 2; mt++) {
            const float4 flo = f[mt * 2];
            const float4 fhi = f[mt * 2 + 1];
            split3(flo.x, flo.y, afr[0][mt][0], afr[1][mt][0], afr[2][mt][0]);
            split3(fhi.x, fhi.y, afr[0][mt][1], afr[1][mt][1], afr[2][mt][1]);
            split3(flo.z, flo.w, afr[0][mt][2], afr[1][mt][2], afr[2][mt][2]);
            split3(fhi.z, fhi.w, afr[0][mt][3], afr[1][mt][3], afr[2][mt][3]);
        }

        // load B fragments for this chunk: bfr[plane][ntile]
        uint2 bfr[3][2];
        #pragma unroll
        for (int p = 0; p < 3; p++)
            #pragma unroll
            for (int nt = 0; nt < 2; nt++) {
                int widx = (((c * 3 + p) * 2 + nt) * 32 + lane) * 2;
                bfr[p][nt] = *(const uint2*)&sB[widx];
            }

        // 6 emulation passes
        #pragma unroll
        for (int ps = 0; ps < 6; ps++) {
            #pragma unroll
            for (int mt = 0; mt < 2; mt++)
                #pragma unroll
                for (int nt = 0; nt < 2; nt++)
                    mma16816(acc[mt][nt], afr[PA[ps]][mt], bfr[PB[ps]][nt]);
        }
    }

    // write D: c0,c1 = row g cols t4*2,t4*2+1; c2,c3 = row g+8
    #pragma unroll
    for (int mt = 0; mt < 2; mt++) {
        int r0 = bbase + wid * 32 + mt * 16 + g;
        #pragma unroll
        for (int nt = 0; nt < 2; nt++) {
            int col = nt * 8 + t4 * 2;
            *(float2*)&g_P[v][r0][col]     = make_float2(acc[mt][nt][0], acc[mt][nt][1]);
            *(float2*)&g_P[v][r0 + 8][col] = make_float2(acc[mt][nt][2], acc[mt][nt][3]);
        }
    }
}

// ---------------------------------------------------------------------------
// Kernel 2: scores + threefry gumbel + argmax -> one-hot outputs (unchanged)
// ---------------------------------------------------------------------------
__device__ __forceinline__ uint32_t rotl32(uint32_t x, int r) {
    return (x << r) | (x >> (32 - r));
}

__device__ __forceinline__ uint32_t threefry_bits(uint32_t key, uint32_t ctr)
{
    const uint32_t ks0 = 0u, ks1 = key, ks2 = 0x1BD11BDAu ^ key;
    uint32_t x0 = ks0;
    uint32_t x1 = ctr + ks1;
#define R4(a,b,cc,d)                                   \
    x0 += x1; x1 = rotl32(x1,(a));  x1 ^= x0;          \
    x0 += x1; x1 = rotl32(x1,(b));  x1 ^= x0;          \
    x0 += x1; x1 = rotl32(x1,(cc)); x1 ^= x0;          \
    x0 += x1; x1 = rotl32(x1,(d));  x1 ^= x0;
    R4(13,15,26,6);   x0 += ks1; x1 += ks2 + 1u;
    R4(17,29,16,24);  x0 += ks2; x1 += ks0 + 2u;
    R4(13,15,26,6);   x0 += ks0; x1 += ks1 + 3u;
    R4(17,29,16,24);  x0 += ks1; x1 += ks2 + 4u;
    R4(13,15,26,6);   x0 += ks2; x1 += ks0 + 5u;
#undef R4
    return x0 ^ x1;
}

__device__ __forceinline__ float gumbel_from_bits(uint32_t bits)
{
    float u = __uint_as_float((bits >> 9) | 0x3f800000u) - 1.0f;
    float val = fmaxf(1e-10f, u * (1.0f - 1e-10f) + 1e-10f);
    return -logf(-logf(val));
}

__global__ __launch_bounds__(64) void score_kernel(float* __restrict__ out)
{
    const int b = blockIdx.x * blockDim.x + threadIdx.x;
    if (b >= B_TOTAL) return;

    float r0[DK], r1[DK];
    #pragma unroll
    for (int t = 0; t < 4; t++) {
        ((float4*)r0)[t] = ((const float4*)&g_P[0][b][0])[t];
        ((float4*)r1)[t] = ((const float4*)&g_P[1][b][0])[t];
    }

    float z0[NSLOT], z1[NSLOT];
    #pragma unroll
    for (int m = 0; m < NSLOT; m++) {
        float wv[DK];
        #pragma unroll
        for (int t = 0; t < 4; t++)
            ((float4*)wv)[t] = ((const float4*)&g_P[2 + m][b][0])[t];

        float s0 = 0.0f, s1 = 0.0f;
        #pragma unroll
        for (int t = 0; t < DK; t++) {
            s0 = fmaf(r0[t], wv[t], s0);
            s1 = fmaf(r1[t], wv[t], s1);
        }
        s0 *= 0.25f;
        s1 *= 0.25f;

        const uint32_t ctr = (uint32_t)(b * NSLOT + m);
        z0[m] = s0 + gumbel_from_bits(threefry_bits(42u, ctr));
        z1[m] = s1 + gumbel_from_bits(threefry_bits(43u, ctr));
    }

    int a0 = 0, a1 = 0;
    float b0v = z0[0], b1v = z1[0];
    #pragma unroll
    for (int m = 1; m < NSLOT; m++) {
        if (z0[m] > b0v) { b0v = z0[m]; a0 = m; }
        if (z1[m] > b1v) { b1v = z1[m]; a1 = m; }
    }

    float* o1 = out + (size_t)b * NSLOT;
    float* o2 = out + (size_t)B_TOTAL * NSLOT + (size_t)b * NSLOT;
    #pragma unroll
    for (int m = 0; m < NSLOT; m++) {
        o1[m] = (m == a0) ? 1.0f : 0.0f;
        o2[m] = (m == a1) ? 1.0f : 0.0f;
    }
}

// ---------------------------------------------------------------------------
extern "C" void kernel_launch(void* const* d_in, const int* in_sizes, int n_in,
                              void* d_out, int out_size)
{
    const float* q  = (const float*)d_in[0];
    const float* kk = (const float*)d_in[1];
    const float* wr = (const float*)d_in[2];
    const float* ww = (const float*)d_in[3];
    float* out = (float*)d_out;

    dim3 grid1(B_TOTAL / MT, NV);
    proj_kernel<<<grid1, THREADS>>>(q, kk, wr, ww);

    score_kernel<<<B_TOTAL / 64, 64>>>(out);
}

// round 10
// speedup vs baseline: 1.7387x; 1.0415x over previous
#include <cuda_runtime.h>
#include <cuda_bf16.h>
#include <cstdint>
#include <math.h>

#define B_TOTAL 32768
#define NSLOT   5
#define D_IN    512
#define DK      16
#define NV      7
#define MT      256          // batches per block
#define NCHK    (D_IN / 16)  // 32 k-chunks of 16
#define THREADS 256

// dynamic smem: [0 .. 16384) words: uint4 B fragments (64KB);
//               [16384 .. 24576) words: raw W (32KB)  -> total 96KB
#define RAW_OFF_W   16384            // word offset of raw W
#define SMEM_BYTES  (96 * 1024)

// projection scratch: P[v][b][k]; v: 0,1 = read slots; 2..6 = write slots
__device__ float g_P[NV][B_TOTAL][DK];

static __device__ __forceinline__ uint32_t tf32_of(float x) {
    uint32_t r; asm("cvt.rna.tf32.f32 %0, %1;" : "=r"(r) : "f"(x)); return r;
}
// exact 2-way split: x = as_float(h) + as_float(l) + O(2^-33 x)
static __device__ __forceinline__ void split2(float x, uint32_t& h, uint32_t& l) {
    h = tf32_of(x);
    l = tf32_of(x - __uint_as_float(h));
}
static __device__ __forceinline__ void mma16808(float* d, const uint32_t* a,
                                                uint32_t b0, uint32_t b1) {
    asm volatile(
        "mma.sync.aligned.m16n8k8.row.col.f32.tf32.tf32.f32 "
        "{%0,%1,%2,%3}, {%4,%5,%6,%7}, {%8,%9}, {%0,%1,%2,%3};"
        : "+f"(d[0]), "+f"(d[1]), "+f"(d[2]), "+f"(d[3])
        : "r"(a[0]), "r"(a[1]), "r"(a[2]), "r"(a[3]), "r"(b0), "r"(b1));
}

// ---------------------------------------------------------------------------
// Kernel 1: projection GEMM on mma.m16n8k8.tf32, fp32 via 2-way split, 4 passes.
// grid = (128, 7), 256 threads (8 warps x 32 batches each).
//
// K-permutation: memory col d = c*16 + 4*t4 + s, where s = 2*ks + reg and
// fragment slot reg0 -> kf=t4, reg1 -> kf=t4+4. A loads become one float4 per
// (row, chunk): (x,y) feed ks=0, (z,w) feed ks=1. B staged in fragment order.
// ---------------------------------------------------------------------------
__global__ __launch_bounds__(THREADS) void proj_kernel(
    const float* __restrict__ q, const float* __restrict__ kk,
    const float* __restrict__ wr, const float* __restrict__ ww)
{
    extern __shared__ uint32_t sh[];
    uint4* sFrag = (uint4*)sh;                       // [c][ks][nt][lane] -> {h0,h1,l0,l1}
    float* sRaw  = (float*)(sh + RAW_OFF_W);         // raw W, 8192 floats

    const int tid  = threadIdx.x;
    const int lane = tid & 31;
    const int wid  = tid >> 5;
    const int g    = lane >> 2;
    const int t4   = lane & 3;

    const int v = blockIdx.y;
    const float* src; const float* W; int slot;
    if (v < 2) { src = q;  slot = v;     W = wr + (size_t)v * D_IN * DK; }
    else       { src = kk; slot = v - 2; W = ww + (size_t)(v - 2) * D_IN * DK; }
    const int bbase = blockIdx.x * MT;

    // ---- phase 0: coalesced raw copy of W (8192 floats) ----
    {
        const float4* Ws = (const float4*)W;
        float4*       Wd = (float4*)sRaw;
        #pragma unroll
        for (int i = 0; i < 8; i++) Wd[tid + i * THREADS] = Ws[tid + i * THREADS];
    }
    __syncthreads();

    // ---- phase 1: scatter-convert W into fragment order ----
    #pragma unroll
    for (int t = 0; t < 16; t++) {
        int j   = tid + t * THREADS;          // 0..4095  = ((c*2+ks)*2+nt)*32+lane
        int jt4 = j & 3;
        int jg  = (j >> 2) & 7;
        int nt  = (j >> 5) & 1;
        int ks  = (j >> 6) & 1;
        int c   = j >> 7;
        int d0  = c * 16 + 4 * jt4 + 2 * ks;  // reg 0
        int n   = nt * 8 + jg;
        float w0 = sRaw[d0 * DK + n];
        float w1 = sRaw[(d0 + 1) * DK + n];
        uint4 V;
        split2(w0, V.x, V.z);
        split2(w1, V.y, V.w);
        sFrag[j] = V;                          // {h(b0), h(b1), l(b0), l(b1)}
    }
    __syncthreads();

    // A pointers: warp rows wid*32 + {g, g+8, g+16, g+24}
    const float* ap[4];
    #pragma unroll
    for (int rh = 0; rh < 4; rh++) {
        int row = bbase + wid * 32 + rh * 8 + g;
        ap[rh] = src + (size_t)row * (NSLOT * D_IN) + (size_t)slot * D_IN + t4 * 4;
    }

    float acc[2][2][4];
    #pragma unroll
    for (int mt = 0; mt < 2; mt++)
        #pragma unroll
        for (int nt = 0; nt < 2; nt++)
            #pragma unroll
            for (int jj = 0; jj < 4; jj++) acc[mt][nt][jj] = 0.0f;

    // prefetch chunk 0
    float4 f[4], pf[4];
    #pragma unroll
    for (int rh = 0; rh < 4; rh++) f[rh] = *(const float4*)(ap[rh]);

    #pragma unroll 2
    for (int c = 0; c < NCHK; c++) {
        // prefetch next chunk while computing this one
        if (c + 1 < NCHK) {
            #pragma unroll
            for (int rh = 0; rh < 4; rh++)
                pf[rh] = *(const float4*)(ap[rh] + (c + 1) * 16);
        }

        #pragma unroll
        for (int ks = 0; ks < 2; ks++) {
            // A fragments for this ks: a0=(g,t4), a1=(g+8,t4), a2=(g,t4+4), a3=(g+8,t4+4)
            uint32_t ah[2][4], al[2][4];
            #pragma unroll
            for (int mt = 0; mt < 2; mt++) {
                const float4 flo = f[2 * mt];
                const float4 fhi = f[2 * mt + 1];
                float e0 = ks ? flo.z : flo.x;
                float e1 = ks ? fhi.z : fhi.x;
                float e2 = ks ? flo.w : flo.y;
                float e3 = ks ? fhi.w : fhi.y;
                split2(e0, ah[mt][0], al[mt][0]);
                split2(e1, ah[mt][1], al[mt][1]);
                split2(e2, ah[mt][2], al[mt][2]);
                split2(e3, ah[mt][3], al[mt][3]);
            }
            #pragma unroll
            for (int nt = 0; nt < 2; nt++) {
                uint4 V = sFrag[((c * 2 + ks) * 2 + nt) * 32 + lane];
                #pragma unroll
                for (int mt = 0; mt < 2; mt++) {
                    mma16808(acc[mt][nt], ah[mt], V.x, V.y);   // hh
                    mma16808(acc[mt][nt], ah[mt], V.z, V.w);   // hl
                    mma16808(acc[mt][nt], al[mt], V.x, V.y);   // lh
                    mma16808(acc[mt][nt], al[mt], V.z, V.w);   // ll
                }
            }
        }

        #pragma unroll
        for (int rh = 0; rh < 4; rh++) f[rh] = pf[rh];
    }

    // write D: c0,c1 = row g cols t4*2,+1 ; c2,c3 = row g+8
    #pragma unroll
    for (int mt = 0; mt < 2; mt++) {
        int r0 = bbase + wid * 32 + mt * 16 + g;
        #pragma unroll
        for (int nt = 0; nt < 2; nt++) {
            int col = nt * 8 + t4 * 2;
            *(float2*)&g_P[v][r0][col]     = make_float2(acc[mt][nt][0], acc[mt][nt][1]);
            *(float2*)&g_P[v][r0 + 8][col] = make_float2(acc[mt][nt][2], acc[mt][nt][3]);
        }
    }
}

// ---------------------------------------------------------------------------
// Kernel 2: scores + threefry gumbel + argmax -> one-hot (2 threads per batch)
// ---------------------------------------------------------------------------
__device__ __forceinline__ uint32_t rotl32(uint32_t x, int r) {
    return (x << r) | (x >> (32 - r));
}

__device__ __forceinline__ uint32_t threefry_bits(uint32_t key, uint32_t ctr)
{
    const uint32_t ks0 = 0u, ks1 = key, ks2 = 0x1BD11BDAu ^ key;
    uint32_t x0 = ks0;
    uint32_t x1 = ctr + ks1;
#define R4(a,b,cc,d)                                   \
    x0 += x1; x1 = rotl32(x1,(a));  x1 ^= x0;          \
    x0 += x1; x1 = rotl32(x1,(b));  x1 ^= x0;          \
    x0 += x1; x1 = rotl32(x1,(cc)); x1 ^= x0;          \
    x0 += x1; x1 = rotl32(x1,(d));  x1 ^= x0;
    R4(13,15,26,6);   x0 += ks1; x1 += ks2 + 1u;
    R4(17,29,16,24);  x0 += ks2; x1 += ks0 + 2u;
    R4(13,15,26,6);   x0 += ks0; x1 += ks1 + 3u;
    R4(17,29,16,24);  x0 += ks1; x1 += ks2 + 4u;
    R4(13,15,26,6);   x0 += ks2; x1 += ks0 + 5u;
#undef R4
    return x0 ^ x1;
}

__device__ __forceinline__ float gumbel_from_bits(uint32_t bits)
{
    float u = __uint_as_float((bits >> 9) | 0x3f800000u) - 1.0f;
    float val = fmaxf(1e-10f, u * (1.0f - 1e-10f) + 1e-10f);
    return -logf(-logf(val));
}

__global__ __launch_bounds__(128) void score_kernel(float* __restrict__ out)
{
    const int idx = blockIdx.x * blockDim.x + threadIdx.x;
    const int b = idx >> 1;
    const int r = idx & 1;
    if (b >= B_TOTAL) return;

    float rv[DK];
    #pragma unroll
    for (int t = 0; t < 4; t++)
        ((float4*)rv)[t] = ((const float4*)&g_P[r][b][0])[t];

    float z[NSLOT];
    #pragma unroll
    for (int m = 0; m < NSLOT; m++) {
        float wv[DK];
        #pragma unroll
        for (int t = 0; t < 4; t++)
            ((float4*)wv)[t] = ((const float4*)&g_P[2 + m][b][0])[t];

        float s = 0.0f;
        #pragma unroll
        for (int t = 0; t < DK; t++) s = fmaf(rv[t], wv[t], s);
        s *= 0.25f;

        const uint32_t ctr = (uint32_t)(b * NSLOT + m);
        z[m] = s + gumbel_from_bits(threefry_bits(42u + (uint32_t)r, ctr));
    }

    int a0 = 0; float bv = z[0];
    #pragma unroll
    for (int m = 1; m < NSLOT; m++)
        if (z[m] > bv) { bv = z[m]; a0 = m; }

    float* o = out + (size_t)r * B_TOTAL * NSLOT + (size_t)b * NSLOT;
    #pragma unroll
    for (int m = 0; m < NSLOT; m++) o[m] = (m == a0) ? 1.0f : 0.0f;
}

// ---------------------------------------------------------------------------
extern "C" void kernel_launch(void* const* d_in, const int* in_sizes, int n_in,
                              void* d_out, int out_size)
{
    const float* q  = (const float*)d_in[0];
    const float* kk = (const float*)d_in[1];
    const float* wr = (const float*)d_in[2];
    const float* ww = (const float*)d_in[3];
    float* out = (float*)d_out;

    cudaFuncSetAttribute(proj_kernel,
                         cudaFuncAttributeMaxDynamicSharedMemorySize, SMEM_BYTES);

    dim3 grid1(B_TOTAL / MT, NV);
    proj_kernel<<<grid1, THREADS, SMEM_BYTES>>>(q, kk, wr, ww);

    score_kernel<<<(2 * B_TOTAL) / 128, 128>>>(out);
}